// round 4
// baseline (speedup 1.0000x reference)
#include <cuda_runtime.h>
#include <cuda_bf16.h>
#include <cstddef>

#define S_LEN 2048
#define B_DIM 64
#define I_DIM 512
#define H_DIM 512
#define BH (B_DIM * H_DIM)          // 32768
#define GX_COLS 1024                // z gates [0,512), n gates [512,1024)

// Scratch: gx[t][b][g], g in 0..1023 maps to weight rows 512+g. 512 MB.
__device__ float g_gx[(size_t)S_LEN * B_DIM * GX_COLS];
// Per-CTA step flags (exact-match protocol -> self-consistent across replays).
__device__ int g_flag[128];

typedef unsigned long long ull;

__device__ __forceinline__ ull fma2(ull a, ull b, ull c) {
    ull d;
    asm("fma.rn.f32x2 %0, %1, %2, %3;" : "=l"(d) : "l"(a), "l"(b), "l"(c));
    return d;
}
__device__ __forceinline__ float sum2(ull u) {
    float lo, hi;
    asm("mov.b64 {%0,%1}, %2;" : "=f"(lo), "=f"(hi) : "l"(u));
    return lo + hi;
}
__device__ __forceinline__ void st_rel(int* p, int v) {
    asm volatile("st.release.gpu.global.b32 [%0], %1;" :: "l"(p), "r"(v) : "memory");
}
__device__ __forceinline__ int ld_acq(const int* p) {
    int v;
    asm volatile("ld.acquire.gpu.global.b32 %0, [%1];" : "=r"(v) : "l"(p) : "memory");
    return v;
}

// ---------------------------------------------------------------------------
// Kernel 1: gx = x @ Wih[512:1536]^T + (bias_ih + bias_hh)[512:1536]
// M=131072, N=1024, K=512. BM=BN=128, BK=16, 256 threads, 8x8 f32x2 tile.
// (unchanged from R2 — passed)
// ---------------------------------------------------------------------------
__global__ void __launch_bounds__(256, 1)
gx_gemm(const float* __restrict__ x, const float* __restrict__ wih,
        const float* __restrict__ bih, const float* __restrict__ bhh) {
    __shared__ ull As2[8 * 130];
    __shared__ ull Bs2[8 * 130];

    const int tid = threadIdx.x;
    const int tx = tid & 15;
    const int ty = tid >> 4;
    const int n0 = blockIdx.x * 128;
    const size_t m0 = (size_t)blockIdx.y * 128;
    const int r = tid >> 1;
    const int half = tid & 1;
    const int kp0 = half * 4;

    float bz[8];
#pragma unroll
    for (int j = 0; j < 8; j++) {
        int n = n0 + tx + 16 * j;
        bz[j] = bih[512 + n] + bhh[512 + n];
    }

    ull acc[8][8];
#pragma unroll
    for (int i = 0; i < 8; i++)
#pragma unroll
        for (int j = 0; j < 8; j++) acc[i][j] = 0ull;

    const float* arow = x + (m0 + r) * 512 + half * 8;
    const float* brow = wih + (size_t)(512 + n0 + r) * 512 + half * 8;

    ulonglong2 A0 = *(const ulonglong2*)(arow);
    ulonglong2 A1 = *(const ulonglong2*)(arow + 4);
    ulonglong2 B0 = *(const ulonglong2*)(brow);
    ulonglong2 B1 = *(const ulonglong2*)(brow + 4);

    for (int kt = 0; kt < 32; kt++) {
        As2[(kp0 + 0) * 130 + r] = A0.x;
        As2[(kp0 + 1) * 130 + r] = A0.y;
        As2[(kp0 + 2) * 130 + r] = A1.x;
        As2[(kp0 + 3) * 130 + r] = A1.y;
        Bs2[(kp0 + 0) * 130 + r] = B0.x;
        Bs2[(kp0 + 1) * 130 + r] = B0.y;
        Bs2[(kp0 + 2) * 130 + r] = B1.x;
        Bs2[(kp0 + 3) * 130 + r] = B1.y;
        __syncthreads();
        if (kt < 31) {
            int ko = (kt + 1) * 16;
            A0 = *(const ulonglong2*)(arow + ko);
            A1 = *(const ulonglong2*)(arow + ko + 4);
            B0 = *(const ulonglong2*)(brow + ko);
            B1 = *(const ulonglong2*)(brow + ko + 4);
        }
#pragma unroll
        for (int kp = 0; kp < 8; kp++) {
            ull av[8], bv[8];
            const ulonglong2* ap = (const ulonglong2*)&As2[kp * 130 + ty * 8];
#pragma unroll
            for (int i2 = 0; i2 < 4; i2++) {
                ulonglong2 t2 = ap[i2];
                av[i2 * 2] = t2.x;
                av[i2 * 2 + 1] = t2.y;
            }
#pragma unroll
            for (int j = 0; j < 8; j++) bv[j] = Bs2[kp * 130 + tx + 16 * j];
#pragma unroll
            for (int i = 0; i < 8; i++)
#pragma unroll
                for (int j = 0; j < 8; j++) acc[i][j] = fma2(av[i], bv[j], acc[i][j]);
        }
        __syncthreads();
    }

#pragma unroll
    for (int i = 0; i < 8; i++) {
        float* orow = g_gx + (m0 + ty * 8 + i) * (size_t)GX_COLS + n0 + tx;
#pragma unroll
        for (int j = 0; j < 8; j++) orow[16 * j] = sum2(acc[i][j]) + bz[j];
    }
}

// ---------------------------------------------------------------------------
// Kernel 2: recurrence. 128 CTAs = 8 groups x 16 CTAs. Group g: batches
// 8g..8g+7. CTA c: h-dims [32c, 32c+32). 512 threads: thread (w,lane) ->
// hd = 2w + (lane>>4), kp = lane&15; owns z & n weight rows of hd over
// k in [32kp, 32kp+32) => 64 weight floats in registers (step-invariant).
// h staged in SMEM swizzled: quad p4 -> slot (p4&7)*16 + (p4>>3), so the
// kp-lanes read 16 consecutive float4s (conflict-free LDS.128).
// Reduction: 4-round shfl bfly over the 16 kp lanes (all lanes get sums);
// lane kp=b does the epilogue for batch b. Inter-CTA sync: per-CTA step
// flags with st.release/ld.acquire, exact-match on t+1.
// ---------------------------------------------------------------------------
__global__ void __launch_bounds__(512, 1)
rec_kernel(const float* __restrict__ h0, const float* __restrict__ whh,
           float* __restrict__ out) {
    __shared__ float4 h4[8][128];   // [b][slot], 16 KB

    const int tid = threadIdx.x;
    const int bx = blockIdx.x;
    const int grp = bx >> 4;
    const int gb = grp * 8;
    const int hd0 = (bx & 15) * 32;
    const int w = tid >> 5;
    const int lane = tid & 31;
    const int kp = lane & 15;
    const int hd = w * 2 + (lane >> 4);
    const int ghd = hd0 + hd;
    const bool ep = (kp < 8);          // epilogue lane for batch eb
    const int eb = kp;

    // Step-invariant weights in registers: z row, n row, 32 k each.
    ulonglong2 wz[8], wn[8];
    {
        const ulonglong2* pz = (const ulonglong2*)(whh + (size_t)(512 + ghd) * 512 + kp * 32);
        const ulonglong2* pn = (const ulonglong2*)(whh + (size_t)(1024 + ghd) * 512 + kp * 32);
#pragma unroll
        for (int q = 0; q < 8; q++) { wz[q] = pz[q]; wn[q] = pn[q]; }
    }

    // h_old element address (for epilogue lanes): element ghd of h4[eb].
    const int equad = ghd >> 2;
    const int eslot = (equad & 7) * 16 + (equad >> 3);
    const int eel = ghd & 3;

    // Stage h(-1) = h_0 (slot-major assignment -> conflict-free STS.128).
#pragma unroll
    for (int it = 0; it < 2; it++) {
        int idx = tid + it * 512;
        int b = idx >> 7, s = idx & 127;
        int f = (s & 15) * 8 + (s >> 4);
        h4[b][s] = __ldcg((const float4*)(h0 + (size_t)(gb + b) * 512) + f);
    }
    __syncthreads();

    for (int t = 0; t < S_LEN; t++) {
        // Prefetch this lane's gx cell (hidden behind ~2k cycles of compute).
        float gz = 0.f, gn = 0.f;
        if (ep) {
            const float* gxt = g_gx + (size_t)t * B_DIM * GX_COLS + (size_t)(gb + eb) * GX_COLS;
            gz = __ldcg(gxt + ghd);
            gn = __ldcg(gxt + 512 + ghd);
        }

        float rzs = 0.f, rns = 0.f;   // selected (b == eb) reduced sums
#pragma unroll
        for (int b = 0; b < 8; b++) {
            ull az0 = 0, az1 = 0, an0 = 0, an1 = 0;
#pragma unroll
            for (int qq = 0; qq < 8; qq++) {
                ulonglong2 h2 = *(const ulonglong2*)&h4[b][qq * 16 + kp];
                az0 = fma2(wz[qq].x, h2.x, az0);
                az1 = fma2(wz[qq].y, h2.y, az1);
                an0 = fma2(wn[qq].x, h2.x, an0);
                an1 = fma2(wn[qq].y, h2.y, an1);
            }
            float vz = sum2(az0) + sum2(az1);
            float vn = sum2(an0) + sum2(an1);
#pragma unroll
            for (int m = 1; m < 16; m <<= 1) {
                vz += __shfl_xor_sync(0xffffffffu, vz, m);
                vn += __shfl_xor_sync(0xffffffffu, vn, m);
            }
            if (ep && b == eb) { rzs = vz; rns = vn; }
        }

        // Epilogue: lane kp=b handles (batch b, this lane's hd).
        if (ep) {
            float h_old = ((const float*)&h4[eb][eslot])[eel];
            float z = 1.0f / (1.0f + expf(-(gz + rzs)));
            float n = tanhf(gn + rns);
            float hv = h_old + z * (n - h_old);
            float* dst = out + (size_t)t * BH + (size_t)(gb + eb) * 512 + ghd;
            __stcg(dst, hv);
            if (t == S_LEN - 1)
                __stcg(out + (size_t)S_LEN * BH + (size_t)(gb + eb) * 512 + ghd, hv);
        }

        // Group barrier via per-CTA flags (release/acquire, exact match).
        __syncthreads();
        if (tid == 0) st_rel(&g_flag[bx], t + 1);
        if (tid < 16) {
            const int* fl = &g_flag[grp * 16 + tid];
            while (ld_acq(fl) != t + 1) __nanosleep(20);
        }
        __syncthreads();

        // Restage h[t] from out (L2) into swizzled SMEM.
#pragma unroll
        for (int it = 0; it < 2; it++) {
            int idx = tid + it * 512;
            int b = idx >> 7, s = idx & 127;
            int f = (s & 15) * 8 + (s >> 4);
            h4[b][s] = __ldcg((const float4*)(out + (size_t)t * BH + (size_t)(gb + b) * 512) + f);
        }
        __syncthreads();
    }
}

extern "C" void kernel_launch(void* const* d_in, const int* in_sizes, int n_in,
                              void* d_out, int out_size) {
    const float* x   = (const float*)d_in[0];  // (S, B, I)
    const float* h0  = (const float*)d_in[1];  // (1, B, H)
    const float* wih = (const float*)d_in[2];  // (3H, I)
    const float* whh = (const float*)d_in[3];  // (3H, H)
    const float* bih = (const float*)d_in[4];  // (3H,)
    const float* bhh = (const float*)d_in[5];  // (3H,)
    float* out = (float*)d_out;                // (1,S,B,H) then (1,B,H)

    dim3 ggrid(8, 1024);
    gx_gemm<<<ggrid, 256>>>(x, wih, bih, bhh);
    rec_kernel<<<128, 512>>>(h0, whh, out);
}

// round 5
// speedup vs baseline: 1.1744x; 1.1744x over previous
#include <cuda_runtime.h>
#include <cuda_bf16.h>
#include <cstddef>

#define S_LEN 2048
#define B_DIM 64
#define I_DIM 512
#define H_DIM 512
#define BH (B_DIM * H_DIM)          // 32768
#define GX_COLS 1024                // z gates [0,512), n gates [512,1024)

// Scratch: gx[t][b][g], g in 0..1023 maps to weight rows 512+g. 512 MB.
__device__ float g_gx[(size_t)S_LEN * B_DIM * GX_COLS];
// Per-CTA step flags; monotone within a launch, compared with >= (stale
// values from a previous replay are < 1, so they never false-release).
__device__ int g_flag[128];

typedef unsigned long long ull;

__device__ __forceinline__ ull fma2(ull a, ull b, ull c) {
    ull d;
    asm("fma.rn.f32x2 %0, %1, %2, %3;" : "=l"(d) : "l"(a), "l"(b), "l"(c));
    return d;
}
__device__ __forceinline__ ull add2(ull a, ull b) {
    ull d;
    asm("add.rn.f32x2 %0, %1, %2;" : "=l"(d) : "l"(a), "l"(b));
    return d;
}
__device__ __forceinline__ float sum2(ull u) {
    float lo, hi;
    asm("mov.b64 {%0,%1}, %2;" : "=f"(lo), "=f"(hi) : "l"(u));
    return lo + hi;
}
__device__ __forceinline__ void st_rel(int* p, int v) {
    asm volatile("st.release.gpu.global.b32 [%0], %1;" :: "l"(p), "r"(v) : "memory");
}
__device__ __forceinline__ int ld_acq(const int* p) {
    int v;
    asm volatile("ld.acquire.gpu.global.b32 %0, [%1];" : "=r"(v) : "l"(p) : "memory");
    return v;
}

// ---------------------------------------------------------------------------
// Kernel 1: gx = x @ Wih[512:1536]^T + (bias_ih + bias_hh)[512:1536]
// M=131072, N=1024, K=512. BM=BN=128, BK=16, 256 threads, 8x8 f32x2 tile.
// (unchanged — proven at R2/R3)
// ---------------------------------------------------------------------------
__global__ void __launch_bounds__(256, 1)
gx_gemm(const float* __restrict__ x, const float* __restrict__ wih,
        const float* __restrict__ bih, const float* __restrict__ bhh) {
    __shared__ ull As2[8 * 130];
    __shared__ ull Bs2[8 * 130];

    const int tid = threadIdx.x;
    const int tx = tid & 15;
    const int ty = tid >> 4;
    const int n0 = blockIdx.x * 128;
    const size_t m0 = (size_t)blockIdx.y * 128;
    const int r = tid >> 1;
    const int half = tid & 1;
    const int kp0 = half * 4;

    float bz[8];
#pragma unroll
    for (int j = 0; j < 8; j++) {
        int n = n0 + tx + 16 * j;
        bz[j] = bih[512 + n] + bhh[512 + n];
    }

    ull acc[8][8];
#pragma unroll
    for (int i = 0; i < 8; i++)
#pragma unroll
        for (int j = 0; j < 8; j++) acc[i][j] = 0ull;

    const float* arow = x + (m0 + r) * 512 + half * 8;
    const float* brow = wih + (size_t)(512 + n0 + r) * 512 + half * 8;

    ulonglong2 A0 = *(const ulonglong2*)(arow);
    ulonglong2 A1 = *(const ulonglong2*)(arow + 4);
    ulonglong2 B0 = *(const ulonglong2*)(brow);
    ulonglong2 B1 = *(const ulonglong2*)(brow + 4);

    for (int kt = 0; kt < 32; kt++) {
        As2[(kp0 + 0) * 130 + r] = A0.x;
        As2[(kp0 + 1) * 130 + r] = A0.y;
        As2[(kp0 + 2) * 130 + r] = A1.x;
        As2[(kp0 + 3) * 130 + r] = A1.y;
        Bs2[(kp0 + 0) * 130 + r] = B0.x;
        Bs2[(kp0 + 1) * 130 + r] = B0.y;
        Bs2[(kp0 + 2) * 130 + r] = B1.x;
        Bs2[(kp0 + 3) * 130 + r] = B1.y;
        __syncthreads();
        if (kt < 31) {
            int ko = (kt + 1) * 16;
            A0 = *(const ulonglong2*)(arow + ko);
            A1 = *(const ulonglong2*)(arow + ko + 4);
            B0 = *(const ulonglong2*)(brow + ko);
            B1 = *(const ulonglong2*)(brow + ko + 4);
        }
#pragma unroll
        for (int kp = 0; kp < 8; kp++) {
            ull av[8], bv[8];
            const ulonglong2* ap = (const ulonglong2*)&As2[kp * 130 + ty * 8];
#pragma unroll
            for (int i2 = 0; i2 < 4; i2++) {
                ulonglong2 t2 = ap[i2];
                av[i2 * 2] = t2.x;
                av[i2 * 2 + 1] = t2.y;
            }
#pragma unroll
            for (int j = 0; j < 8; j++) bv[j] = Bs2[kp * 130 + tx + 16 * j];
#pragma unroll
            for (int i = 0; i < 8; i++)
#pragma unroll
                for (int j = 0; j < 8; j++) acc[i][j] = fma2(av[i], bv[j], acc[i][j]);
        }
        __syncthreads();
    }

#pragma unroll
    for (int i = 0; i < 8; i++) {
        float* orow = g_gx + (m0 + ty * 8 + i) * (size_t)GX_COLS + n0 + tx;
#pragma unroll
        for (int j = 0; j < 8; j++) orow[16 * j] = sum2(acc[i][j]) + bz[j];
    }
}

// ---------------------------------------------------------------------------
// Kernel 2: recurrence. 128 CTAs = 8 groups x 16 CTAs; group g owns batches
// 8g..8g+7, CTA c owns h-dims [32c, 32c+32). 256 threads (8 warps).
// Thread (wid, lane): hdg = wid*2 + (lane>>4) -> hd pair {hd0+2hdg, +1};
// kp = lane&15 -> k in [32kp, 32kp+32). Owns rows {z0,z1,n0,n1} of the hd
// pair over its k slice: 128 weight floats, registers, step-invariant.
// Per step: 32 partial outputs (4 rows x 8 batches) per thread, then ONE
// recursive-halving reduce-scatter over the 16 kp lanes (30 shfl) leaving
// lane kp = b*2+hdbit with the (z,n) sums of (batch b, hd0+2hdg+hdbit).
// Every lane does exactly one h-update.
// ---------------------------------------------------------------------------
__global__ void __launch_bounds__(256, 1)
rec_kernel(const float* __restrict__ h0, const float* __restrict__ whh,
           float* __restrict__ out) {
    __shared__ float4 h_s4[8][8][17];   // [b][q][kp] swizzled, k=(kp*8+q)*4+e

    const int tid = threadIdx.x;
    const int bx = blockIdx.x;
    const int grp = bx >> 4;
    const int gb = grp * 8;
    const int hd0 = (bx & 15) * 32;
    const int lane = tid & 31;
    const int wid = tid >> 5;
    const int kp = lane & 15;
    const int hdg = wid * 2 + (lane >> 4);
    const int rowhd = hd0 + hdg * 2;          // hd of rows z0/n0 (z1/n1 = +1)

    // Epilogue cell of THIS lane after reduce-scatter:
    const int eb = kp >> 1;                    // batch within group
    const int ghd = rowhd + (kp & 1);          // its h dimension
    const int equad = ghd >> 2;
    const int eslot_q = equad & 7, eslot_p = equad >> 3, eel = ghd & 3;

    // Step-invariant weights in registers (128 floats).
    ulonglong2 wz0[8], wz1[8], wn0[8], wn1[8];
    {
        const ulonglong2* pz0 = (const ulonglong2*)(whh + (size_t)(512 + rowhd) * 512 + kp * 32);
        const ulonglong2* pz1 = (const ulonglong2*)(whh + (size_t)(513 + rowhd) * 512 + kp * 32);
        const ulonglong2* pn0 = (const ulonglong2*)(whh + (size_t)(1024 + rowhd) * 512 + kp * 32);
        const ulonglong2* pn1 = (const ulonglong2*)(whh + (size_t)(1025 + rowhd) * 512 + kp * 32);
#pragma unroll
        for (int q = 0; q < 8; q++) {
            wz0[q] = pz0[q]; wz1[q] = pz1[q];
            wn0[q] = pn0[q]; wn1[q] = pn1[q];
        }
    }

    // Stage h(-1) = h_0 into swizzled SMEM.
    {
        int b = tid >> 5, rr = tid & 31;
        const float4* src = (const float4*)(h0 + (size_t)(gb + b) * 512);
#pragma unroll
        for (int j = 0; j < 4; j++) {
            int k4 = j * 32 + rr;
            h_s4[b][k4 & 7][k4 >> 3] = __ldcg(src + k4);
        }
    }
    __syncthreads();

    for (int t = 0; t < S_LEN; t++) {
        // Prefetch this lane's gx cell early (hidden behind the fma block).
        const float* gxt = g_gx + (size_t)t * B_DIM * GX_COLS + (size_t)(gb + eb) * GX_COLS;
        float pgz = __ldcg(gxt + ghd);
        float pgn = __ldcg(gxt + 512 + ghd);

        // 32 partial outputs: cur[i], i = b*4 + hdbit*2 + gate (z=0,n=1).
        float cur[32];
#pragma unroll
        for (int b = 0; b < 8; b++) {
            ull az0 = 0, az1 = 0, an0 = 0, an1 = 0;
            ull bz0 = 0, bz1 = 0, bn0 = 0, bn1 = 0;
#pragma unroll
            for (int q = 0; q < 8; q++) {
                ulonglong2 h2 = *(const ulonglong2*)&h_s4[b][q][kp];
                az0 = fma2(wz0[q].x, h2.x, az0);
                bz0 = fma2(wz0[q].y, h2.y, bz0);
                az1 = fma2(wz1[q].x, h2.x, az1);
                bz1 = fma2(wz1[q].y, h2.y, bz1);
                an0 = fma2(wn0[q].x, h2.x, an0);
                bn0 = fma2(wn0[q].y, h2.y, bn0);
                an1 = fma2(wn1[q].x, h2.x, an1);
                bn1 = fma2(wn1[q].y, h2.y, bn1);
            }
            cur[b * 4 + 0] = sum2(add2(az0, bz0));   // z, hdbit 0
            cur[b * 4 + 1] = sum2(add2(an0, bn0));   // n, hdbit 0
            cur[b * 4 + 2] = sum2(add2(az1, bz1));   // z, hdbit 1
            cur[b * 4 + 3] = sum2(add2(an1, bn1));   // n, hdbit 1
        }
        // Index map check: i = b*4 + hdbit*2 + gate. Stored above as
        // [b*4+0]=z/hd0, [b*4+1]=n/hd0, [b*4+2]=z/hd1, [b*4+3]=n/hd1
        // -> i bits: [4:2]=b, [1]=hdbit, [0]=gate. Final owner lane
        // kp = b*2 + hdbit keeps {i=2*kp (z), i=2*kp+1 (n)}.
        {
            int n = 32;
#pragma unroll
            for (int m = 8; m >= 1; m >>= 1) {
                int halfn = n >> 1;
                bool up = (kp & m) != 0;
#pragma unroll
                for (int j = 0; j < 16; j++) {
                    if (j < halfn) {
                        float keep = up ? cur[halfn + j] : cur[j];
                        float send = up ? cur[j] : cur[halfn + j];
                        float rec = __shfl_xor_sync(0xffffffffu, send, m);
                        cur[j] = keep + rec;
                    }
                }
                n = halfn;
            }
        }

        // Epilogue: every lane updates one (batch eb, dim ghd).
        {
            float h_old = ((const float*)&h_s4[eb][eslot_q][eslot_p])[eel];
            float z = 1.0f / (1.0f + expf(-(pgz + cur[0])));
            float nn = tanhf(pgn + cur[1]);
            float hv = h_old + z * (nn - h_old);
            __stcg(out + (size_t)t * BH + (size_t)(gb + eb) * 512 + ghd, hv);
            if (t == S_LEN - 1)
                __stcg(out + (size_t)S_LEN * BH + (size_t)(gb + eb) * 512 + ghd, hv);
        }

        // Group barrier: syncthreads orders all CTA stores before tid0's
        // release; pollers use acquire with >= (fast CTAs may be ahead).
        __syncthreads();
        if (tid == 0) st_rel(&g_flag[bx], t + 1);
        if (tid < 16) {
            const int* fl = &g_flag[grp * 16 + tid];
            while (ld_acq(fl) < t + 1) __nanosleep(20);
        }
        __syncthreads();

        // Restage h[t] from out (L2) into swizzled SMEM.
        {
            int b = tid >> 5, rr = tid & 31;
            const float4* src = (const float4*)(out + (size_t)t * BH + (size_t)(gb + b) * 512);
#pragma unroll
            for (int j = 0; j < 4; j++) {
                int k4 = j * 32 + rr;
                h_s4[b][k4 & 7][k4 >> 3] = __ldcg(src + k4);
            }
        }
        __syncthreads();
    }
}

extern "C" void kernel_launch(void* const* d_in, const int* in_sizes, int n_in,
                              void* d_out, int out_size) {
    const float* x   = (const float*)d_in[0];  // (S, B, I)
    const float* h0  = (const float*)d_in[1];  // (1, B, H)
    const float* wih = (const float*)d_in[2];  // (3H, I)
    const float* whh = (const float*)d_in[3];  // (3H, H)
    const float* bih = (const float*)d_in[4];  // (3H,)
    const float* bhh = (const float*)d_in[5];  // (3H,)
    float* out = (float*)d_out;                // (1,S,B,H) then (1,B,H)

    dim3 ggrid(8, 1024);
    gx_gemm<<<ggrid, 256>>>(x, wih, bih, bhh);
    rec_kernel<<<128, 256>>>(h0, whh, out);
}